// round 16
// baseline (speedup 1.0000x reference)
#include <cuda_runtime.h>
#include <math.h>

#define BB    256
#define SS    512
#define OBS   64
#define ZD    16
#define HID   256
#define TPD   128      // T*PD
#define NITER 4
#define NEL   64
#define TILE  64
#define XROW  64       // smem row stride (256B): RT scheme is conflict-free & aligned
#define NTHR  512

// ---- packed f32x2 helpers ----
#define PACK2(dst, lo, hi) asm("mov.b64 %0, {%1, %2};" : "=l"(dst) : "f"(lo), "f"(hi))
#define UNPACK2(lo, hi, src) asm("mov.b64 {%0, %1}, %2;" : "=f"(lo), "=f"(hi) : "l"(src))
#define FMA2(acc, a, b) asm("fma.rn.f32x2 %0, %1, %2, %0;" : "+l"(acc) : "l"(a), "l"(b))

// ---------------- device scratch (no allocs allowed) ----------------
__device__ float g_mu[BB * ZD];
__device__ float g_std[BB * ZD];
__device__ float g_best_score[BB];
__device__ float g_best_z[BB * ZD];
__device__ float g_score[BB * SS];
__device__ float g_z[(size_t)BB * SS * ZD];
__device__ float g_base_mu[BB * HID];
__device__ float g_base_risk[BB * HID];

// ---------------- encoder + per-b layer1 base vectors ----------------
__global__ void encoder_kernel(const float* __restrict__ s0,
                               const float* __restrict__ enc_w1, const float* __restrict__ enc_b1,
                               const float* __restrict__ enc_w2, const float* __restrict__ enc_b2,
                               const float* __restrict__ zmu_w,  const float* __restrict__ zmu_b,
                               const float* __restrict__ zls_w,  const float* __restrict__ zls_b,
                               const float* __restrict__ mu_w1,  const float* __restrict__ mu_b1,
                               const float* __restrict__ risk_w1, const float* __restrict__ risk_b1)
{
    __shared__ float s0s[OBS];
    __shared__ float h1[HID];
    __shared__ float h2[HID];
    int b = blockIdx.x;
    int t = threadIdx.x;

    if (t < OBS) s0s[t] = s0[b * OBS + t];
    __syncthreads();

    // base vectors: s0-part of mu/risk layer1 (row-independent)
    {
        float bm = mu_b1[t], br = risk_b1[t];
        for (int k = 0; k < OBS; k++) {
            float sv = s0s[k];
            bm += sv * mu_w1[k * HID + t];
            br += sv * risk_w1[k * HID + t];
        }
        g_base_mu[b * HID + t]   = bm;
        g_base_risk[b * HID + t] = br;
    }

    float a = enc_b1[t];
    for (int k = 0; k < OBS; k++) a += s0s[k] * enc_w1[k * HID + t];
    h1[t] = fmaxf(a, 0.f);
    __syncthreads();

    a = enc_b2[t];
    for (int k = 0; k < HID; k++) a += h1[k] * enc_w2[k * HID + t];
    h2[t] = fmaxf(a, 0.f);
    __syncthreads();

    if (t < ZD) {
        float m = zmu_b[t], ls = zls_b[t];
        for (int k = 0; k < HID; k++) {
            float hv = h2[k];
            m  += hv * zmu_w[k * ZD + t];
            ls += hv * zls_w[k * ZD + t];
        }
        ls = fminf(fmaxf(ls, -4.f), 2.f);
        g_mu[b * ZD + t]     = m;
        g_std[b * ZD + t]    = expf(ls);
        g_best_z[b * ZD + t] = m;
    }
    if (t == 0) g_best_score[b] = -INFINITY;
}

// ---------------- register-tiled GEMM: warp = 16 cols x 64 rows ----------------
// lane (cg = lane>>3, rp = lane&7) owns cols jb..jb+3, rows {rp*4..+3} U {32+rp*4..+3}
// XROW=64 -> x LDS.128 rows are 128B-aligned contiguous: 1 wf each, conflict-free.
template<int K, int LDW, bool HAS_BIAS, bool DO_RELU>
__device__ __forceinline__ void gemm_rt(const float* __restrict__ xs,   // smem [K][XROW]
                                        const float* __restrict__ W,    // global [K][LDW]
                                        const float* __restrict__ bias, // [.. jb+3] or null
                                        float* __restrict__ outbuf,     // smem rows jb..jb+3
                                        int jb)
{
    const int lane = threadIdx.x & 31;
    const int rp   = lane & 7;
    const int rlo  = rp * 4;
    const int rhi  = 32 + rp * 4;

    unsigned long long acc[4][4];
    if (HAS_BIAS) {
        float4 bq = *reinterpret_cast<const float4*>(bias + jb);
        float bv[4] = {bq.x, bq.y, bq.z, bq.w};
#pragma unroll
        for (int c = 0; c < 4; c++) {
            unsigned long long b2; PACK2(b2, bv[c], bv[c]);
#pragma unroll
            for (int r = 0; r < 4; r++) acc[c][r] = b2;
        }
    } else {
#pragma unroll
        for (int c = 0; c < 4; c++)
#pragma unroll
            for (int r = 0; r < 4; r++) acc[c][r] = 0ull;
    }

    constexpr int PF = 4;
    const float* Wp = W + jb;
    float4 wr[PF];
#pragma unroll
    for (int p = 0; p < PF; p++)
        wr[p] = (p < K) ? *reinterpret_cast<const float4*>(Wp + p * LDW)
                        : make_float4(0.f, 0.f, 0.f, 0.f);

#pragma unroll 4
    for (int k = 0; k < K; k++) {
        float4 wq = wr[k & 3];
        int kn = k + PF;
        if (kn < K) wr[k & 3] = *reinterpret_cast<const float4*>(Wp + kn * LDW);
        ulonglong2 xlo = *reinterpret_cast<const ulonglong2*>(xs + k * XROW + rlo);
        ulonglong2 xhi = *reinterpret_cast<const ulonglong2*>(xs + k * XROW + rhi);
        float wv[4] = {wq.x, wq.y, wq.z, wq.w};
#pragma unroll
        for (int c = 0; c < 4; c++) {
            unsigned long long w2; PACK2(w2, wv[c], wv[c]);
            FMA2(acc[c][0], xlo.x, w2);
            FMA2(acc[c][1], xlo.y, w2);
            FMA2(acc[c][2], xhi.x, w2);
            FMA2(acc[c][3], xhi.y, w2);
        }
    }

#pragma unroll
    for (int c = 0; c < 4; c++) {
        float* o = outbuf + (jb + c) * XROW;
        float f0, f1, f2, f3;
        UNPACK2(f0, f1, acc[c][0]); UNPACK2(f2, f3, acc[c][1]);
        if (DO_RELU) { f0 = fmaxf(f0, 0.f); f1 = fmaxf(f1, 0.f); f2 = fmaxf(f2, 0.f); f3 = fmaxf(f3, 0.f); }
        *reinterpret_cast<float4*>(o + rlo) = make_float4(f0, f1, f2, f3);
        UNPACK2(f0, f1, acc[c][2]); UNPACK2(f2, f3, acc[c][3]);
        if (DO_RELU) { f0 = fmaxf(f0, 0.f); f1 = fmaxf(f1, 0.f); f2 = fmaxf(f2, 0.f); f3 = fmaxf(f3, 0.f); }
        *reinterpret_cast<float4*>(o + rhi) = make_float4(f0, f1, f2, f3);
    }
}

// ---------------- per-sample score ----------------
__global__ void __launch_bounds__(NTHR, 1) score_kernel(int iter,
    const float* __restrict__ s0,  const float* __restrict__ eps,
    const float* __restrict__ mu_w1,
    const float* __restrict__ mu_w2,  const float* __restrict__ mu_b2,
    const float* __restrict__ mu_w3,  const float* __restrict__ mu_b3,
    const float* __restrict__ sig_w1, const float* __restrict__ sig_b1,
    const float* __restrict__ sig_w2, const float* __restrict__ sig_b2,
    const float* __restrict__ sig_w3, const float* __restrict__ sig_b3,
    const float* __restrict__ risk_w1,
    const float* __restrict__ risk_w2, const float* __restrict__ risk_b2,
    const float* __restrict__ risk_w3, const float* __restrict__ risk_b3)
{
    extern __shared__ float smem[];
    float* xs   = smem;                       // [16][XROW]  (z only)
    float* bufA = smem + ZD * XROW;           // [256][XROW]
    float* bufB = bufA + HID * XROW;          // [256][XROW]

    __shared__ float red_s[NTHR];
    __shared__ float intent_s[TILE], agency_s[TILE];

    int bidx   = blockIdx.x;
    int b      = bidx >> 3;                   // SS/TILE = 8
    int s_base = (bidx & 7) * TILE;
    int t      = threadIdx.x;
    int warp   = t >> 5;
    int lane   = t & 31;
    int cg     = lane >> 3;
    const int jb = warp * 16 + cg * 4;        // this thread's 4 cols (layer-1/2 GEMMs)

    // stage z transposed into smem, write z to global (2 elems per thread)
    {
#pragma unroll
        for (int i = 0; i < 2; i++) {
            int e = t + NTHR * i;
            int d = e & 15;
            int r = e >> 4;
            int s = s_base + r;
            float ev = eps[((((size_t)iter * BB + b) * SS) + s) * ZD + d];
            float v  = g_mu[b * ZD + d] + g_std[b * ZD + d] * ev;
            g_z[((size_t)(b * SS + s)) * ZD + d] = v;
            xs[d * XROW + r] = v;
        }
    }
    __syncthreads();

    // ---- mu path ----
    gemm_rt<ZD, HID, true, true>(xs, mu_w1 + OBS * HID, g_base_mu + b * HID, bufA, jb);
    __syncthreads();
    gemm_rt<HID, HID, true, true>(bufA, mu_w2, mu_b2, bufB, jb);
    __syncthreads();
    {   // head: cols 126,127 of mu_w3; 4 ksegs(64k) x 2 cols x 64 rows = 512
        int kseg = t >> 7;
        int c    = (t >> 6) & 1;
        int r    = t & 63;
        const float* wc = mu_w3 + (TPD - 2) + c;
        float acc = 0.f;
        int k0 = kseg * 64;
        for (int k = k0; k < k0 + 64; k++) acc += bufB[k * XROW + r] * wc[k * TPD];
        red_s[t] = acc;
    }
    __syncthreads();
    if (t < TILE) {   // fused combine + intent
        float m0 = mu_b3[TPD - 2], m1 = mu_b3[TPD - 1];
#pragma unroll
        for (int seg = 0; seg < 4; seg++) {
            m0 += red_s[seg * 128 + t];
            m1 += red_s[seg * 128 + 64 + t];
        }
        float d0 = m0 - s0[b * OBS + 2];
        float d1 = m1 - s0[b * OBS + 3];
        intent_s[t] = d0 * d0 + d1 * d1;
    }
    // no barrier needed: next GEMM writes bufA, reads xs; red_s next written
    // only after a later barrier; intent_s consumed at the very end

    // ---- sigma path ----
    gemm_rt<ZD, HID, true, true>(xs, sig_w1, sig_b1, bufA, jb);
    __syncthreads();
    gemm_rt<HID, HID, true, true>(bufA, sig_w2, sig_b2, bufB, jb);
    __syncthreads();
    {   // layer3: 128 cols, K=256 split in 2 halves; warps 0-7 = kg0, 8-15 = kg1
        int kg  = warp >> 3;
        int jb3 = (warp & 7) * 16 + cg * 4;   // cols 0..127
        gemm_rt<128, TPD, false, false>(bufB + kg * 128 * XROW,
                                        sig_w3 + (size_t)kg * 128 * TPD,
                                        (const float*)0,
                                        bufA + kg * 128 * XROW, jb3);
    }
    __syncthreads();
    {   // agency: combine K-halves + bias + clip, reduce 128 cols (8 colgroups x 64 rows)
        int g = t >> 6;
        int r = t & 63;
        float sum = 0.f;
        for (int j = g * 16; j < g * 16 + 16; j++) {
            float v = sig_b3[j] + bufA[j * XROW + r] + bufA[(j + 128) * XROW + r];
            sum += fminf(fmaxf(v, -4.f), 3.f);
        }
        red_s[t] = sum;
    }
    __syncthreads();
    if (t < TILE) {
        float sum = 0.f;
#pragma unroll
        for (int g = 0; g < 8; g++) sum += red_s[g * 64 + t];
        agency_s[t] = -sum * (1.f / TPD);
    }
    __syncthreads();

    // ---- risk path ----
    gemm_rt<ZD, HID, true, true>(xs, risk_w1 + OBS * HID, g_base_risk + b * HID, bufA, jb);
    __syncthreads();
    gemm_rt<HID, HID, true, true>(bufA, risk_w2, risk_b2, bufB, jb);
    __syncthreads();
    {   // layer3: 64 outputs, k split over 8 segs of 32 (8 ksegs x 64 rows = 512)
        int kseg = t >> 6;
        int r    = t & 63;
        float acc = 0.f;
        int k0 = kseg * 32;
        for (int k = k0; k < k0 + 32; k++) acc += bufB[k * XROW + r] * risk_w3[k];
        red_s[t] = acc;
    }
    __syncthreads();
    if (t < TILE) {
        float acc = risk_b3[0];
#pragma unroll
        for (int p = 0; p < 8; p++) acc += red_s[p * 64 + t];
        float risk = 1.f / (1.f + expf(-acc));
        float score = -intent_s[t] + 0.5f * agency_s[t] - risk;
        g_score[b * SS + s_base + t] = score;
    }
}

// ---------------- top-k + CEM update ----------------
__global__ void topk_kernel(int write_out, float* __restrict__ out)
{
    __shared__ float keys[SS];
    __shared__ int   ids[SS];
    __shared__ float ps[16 * ZD];
    __shared__ float mean_s[ZD];
    __shared__ int   flag_s, bidx_s;

    int b = blockIdx.x;
    int t = threadIdx.x;

    keys[t]       = g_score[b * SS + t];       ids[t]       = t;
    keys[t + 256] = g_score[b * SS + t + 256]; ids[t + 256] = t + 256;

    // bitonic sort ascending (512 elems, 256 threads)
    for (int k2 = 2; k2 <= SS; k2 <<= 1)
        for (int j = k2 >> 1; j > 0; j >>= 1) {
            __syncthreads();
            int i = ((t & ~(j - 1)) << 1) | (t & (j - 1));
            int p = i | j;
            bool up = ((i & k2) == 0);
            float a = keys[i], c = keys[p];
            if ((a > c) == up) {
                keys[i] = c; keys[p] = a;
                int tmp = ids[i]; ids[i] = ids[p]; ids[p] = tmp;
            }
        }
    __syncthreads();

    // elite mean (top-64 = positions [448, 512))
    int d = t & 15, part = t >> 4;
    float sum = 0.f;
    for (int e = part * 4; e < part * 4 + 4; e++) {
        int si = ids[SS - NEL + e];
        sum += g_z[((size_t)(b * SS + si)) * ZD + d];
    }
    ps[part * ZD + d] = sum;
    __syncthreads();
    if (t < ZD) {
        float m = 0.f;
        for (int p2 = 0; p2 < 16; p2++) m += ps[p2 * ZD + t];
        mean_s[t] = m * (1.f / NEL);
    }
    __syncthreads();

    // elite var (ddof=1)
    sum = 0.f;
    for (int e = part * 4; e < part * 4 + 4; e++) {
        int si = ids[SS - NEL + e];
        float v = g_z[((size_t)(b * SS + si)) * ZD + d] - mean_s[d];
        sum += v * v;
    }
    ps[part * ZD + d] = sum;
    __syncthreads();

    if (t == 0) {
        float v0 = keys[SS - 1];
        int better = v0 > g_best_score[b];
        flag_s = better; bidx_s = ids[SS - 1];
        if (better) g_best_score[b] = v0;
    }
    __syncthreads();

    if (t < ZD) {
        float var  = 0.f;
        for (int p2 = 0; p2 < 16; p2++) var += ps[p2 * ZD + t];
        float nstd = sqrtf(var * (1.f / (NEL - 1)));
        float nmu  = mean_s[t];
        float om = g_mu[b * ZD + t], os = g_std[b * ZD + t];
        g_mu[b * ZD + t]  = 0.25f * om + 0.75f * nmu;
        g_std[b * ZD + t] = fmaxf(0.25f * os + 0.75f * nstd, 0.2f);
        if (flag_s) g_best_z[b * ZD + t] = g_z[((size_t)(b * SS + bidx_s)) * ZD + t];
    }

    if (write_out) {
        __syncthreads();
        if (t < ZD)  out[b * 17 + t]  = g_best_z[b * ZD + t];
        if (t == ZD) out[b * 17 + ZD] = g_best_score[b];
    }
}

// ---------------- launch ----------------
extern "C" void kernel_launch(void* const* d_in, const int* in_sizes, int n_in,
                              void* d_out, int out_size)
{
    const float* s0      = (const float*)d_in[0];
    const float* eps     = (const float*)d_in[1];
    const float* enc_w1  = (const float*)d_in[2];
    const float* enc_b1  = (const float*)d_in[3];
    const float* enc_w2  = (const float*)d_in[4];
    const float* enc_b2  = (const float*)d_in[5];
    const float* zmu_w   = (const float*)d_in[6];
    const float* zmu_b   = (const float*)d_in[7];
    const float* zls_w   = (const float*)d_in[8];
    const float* zls_b   = (const float*)d_in[9];
    const float* mu_w1   = (const float*)d_in[10];
    const float* mu_b1   = (const float*)d_in[11];
    const float* mu_w2   = (const float*)d_in[12];
    const float* mu_b2   = (const float*)d_in[13];
    const float* mu_w3   = (const float*)d_in[14];
    const float* mu_b3   = (const float*)d_in[15];
    const float* sig_w1  = (const float*)d_in[16];
    const float* sig_b1  = (const float*)d_in[17];
    const float* sig_w2  = (const float*)d_in[18];
    const float* sig_b2  = (const float*)d_in[19];
    const float* sig_w3  = (const float*)d_in[20];
    const float* sig_b3  = (const float*)d_in[21];
    const float* risk_w1 = (const float*)d_in[22];
    const float* risk_b1 = (const float*)d_in[23];
    const float* risk_w2 = (const float*)d_in[24];
    const float* risk_b2 = (const float*)d_in[25];
    const float* risk_w3 = (const float*)d_in[26];
    const float* risk_b3 = (const float*)d_in[27];

    const int SMEM_BYTES = (ZD + 2 * HID) * XROW * (int)sizeof(float);  // 135,168 B
    cudaFuncSetAttribute(score_kernel, cudaFuncAttributeMaxDynamicSharedMemorySize, SMEM_BYTES);

    encoder_kernel<<<BB, 256>>>(s0, enc_w1, enc_b1, enc_w2, enc_b2,
                                zmu_w, zmu_b, zls_w, zls_b,
                                mu_w1, mu_b1, risk_w1, risk_b1);

    for (int i = 0; i < NITER; i++) {
        score_kernel<<<BB * (SS / TILE), NTHR, SMEM_BYTES>>>(i, s0, eps,
            mu_w1, mu_w2, mu_b2, mu_w3, mu_b3,
            sig_w1, sig_b1, sig_w2, sig_b2, sig_w3, sig_b3,
            risk_w1, risk_w2, risk_b2, risk_w3, risk_b3);
        topk_kernel<<<BB, 256>>>(i == NITER - 1 ? 1 : 0, (float*)d_out);
    }
}

// round 17
// speedup vs baseline: 1.7982x; 1.7982x over previous
#include <cuda_runtime.h>
#include <math.h>

#define BB    256
#define SS    512
#define OBS   64
#define ZD    16
#define HID   256
#define TPD   128      // T*PD
#define NITER 4
#define NEL   64
#define TILE  64
#define XROW  68       // smem row stride in floats (272B, multiple of 16B)
#define NTHR  512

// ---- packed f32x2 helpers ----
#define PACK2(dst, lo, hi) asm("mov.b64 %0, {%1, %2};" : "=l"(dst) : "f"(lo), "f"(hi))
#define UNPACK2(lo, hi, src) asm("mov.b64 {%0, %1}, %2;" : "=f"(lo), "=f"(hi) : "l"(src))
#define FMA2(acc, a, b) asm("fma.rn.f32x2 %0, %1, %2, %0;" : "+l"(acc) : "l"(a), "l"(b))
// per-row-group barrier: 128 threads, ids 1..4
#define GBAR(rg) asm volatile("bar.sync %0, 128;" :: "r"((rg) + 1) : "memory")

// ---------------- device scratch (no allocs allowed) ----------------
__device__ float g_mu[BB * ZD];
__device__ float g_std[BB * ZD];
__device__ float g_best_score[BB];
__device__ float g_best_z[BB * ZD];
__device__ float g_score[BB * SS];
__device__ float g_z[(size_t)BB * SS * ZD];
__device__ float g_base_mu[BB * HID];
__device__ float g_base_risk[BB * HID];

// ---------------- encoder + per-b layer1 base vectors ----------------
__global__ void encoder_kernel(const float* __restrict__ s0,
                               const float* __restrict__ enc_w1, const float* __restrict__ enc_b1,
                               const float* __restrict__ enc_w2, const float* __restrict__ enc_b2,
                               const float* __restrict__ zmu_w,  const float* __restrict__ zmu_b,
                               const float* __restrict__ zls_w,  const float* __restrict__ zls_b,
                               const float* __restrict__ mu_w1,  const float* __restrict__ mu_b1,
                               const float* __restrict__ risk_w1, const float* __restrict__ risk_b1)
{
    __shared__ float s0s[OBS];
    __shared__ float h1[HID];
    __shared__ float h2[HID];
    int b = blockIdx.x;
    int t = threadIdx.x;

    if (t < OBS) s0s[t] = s0[b * OBS + t];
    __syncthreads();

    // base vectors: s0-part of mu/risk layer1 (row-independent)
    {
        float bm = mu_b1[t], br = risk_b1[t];
        for (int k = 0; k < OBS; k++) {
            float sv = s0s[k];
            bm += sv * mu_w1[k * HID + t];
            br += sv * risk_w1[k * HID + t];
        }
        g_base_mu[b * HID + t]   = bm;
        g_base_risk[b * HID + t] = br;
    }

    float a = enc_b1[t];
    for (int k = 0; k < OBS; k++) a += s0s[k] * enc_w1[k * HID + t];
    h1[t] = fmaxf(a, 0.f);
    __syncthreads();

    a = enc_b2[t];
    for (int k = 0; k < HID; k++) a += h1[k] * enc_w2[k * HID + t];
    h2[t] = fmaxf(a, 0.f);
    __syncthreads();

    if (t < ZD) {
        float m = zmu_b[t], ls = zls_b[t];
        for (int k = 0; k < HID; k++) {
            float hv = h2[k];
            m  += hv * zmu_w[k * ZD + t];
            ls += hv * zls_w[k * ZD + t];
        }
        ls = fminf(fmaxf(ls, -4.f), 2.f);
        g_mu[b * ZD + t]     = m;
        g_std[b * ZD + t]    = expf(ls);
        g_best_z[b * ZD + t] = m;
    }
    if (t == 0) g_best_score[b] = -INFINITY;
}

// ---------------- fused tile GEMM, 2 adjacent cols x 16 rows per thread ----------------
// out[j][r] = act(bias[j] + sum_k xs[k][r]*W[k][j]) ; all deps group-local (rg = t>>7)
template<int K, bool DO_RELU>
__device__ __forceinline__ void gemm_tile(const float* __restrict__ xs,   // smem [K][XROW]
                                          const float* __restrict__ W,    // global [K][256]
                                          const float* __restrict__ bias, // global/scratch [256]
                                          float* __restrict__ outbuf)     // smem [256][XROW]
{
    const int t  = threadIdx.x;
    const int j0 = (t & 127) * 2;             // adjacent cols j0, j0+1
    const int rg = t >> 7;                    // rows [rg*16, rg*16+16)
    const float* xbase = xs + rg * 16;

    unsigned long long accA[8], accB[8];
    {
        float2 bb = *reinterpret_cast<const float2*>(bias + j0);
        unsigned long long b02, b12; PACK2(b02, bb.x, bb.x); PACK2(b12, bb.y, bb.y);
#pragma unroll
        for (int r = 0; r < 8; r++) { accA[r] = b02; accB[r] = b12; }
    }

    constexpr int PF = 8;
    float2 wr[PF];
#pragma unroll
    for (int p = 0; p < PF; p++)
        wr[p] = (p < K) ? *reinterpret_cast<const float2*>(W + p * HID + j0)
                        : make_float2(0.f, 0.f);

#pragma unroll 8
    for (int k = 0; k < K; k++) {
        float2 wc = wr[k & 7];
        int kn = k + PF;
        if (kn < K) wr[k & 7] = *reinterpret_cast<const float2*>(W + kn * HID + j0);
        unsigned long long w2a, w2b; PACK2(w2a, wc.x, wc.x); PACK2(w2b, wc.y, wc.y);
        const ulonglong2* xr = reinterpret_cast<const ulonglong2*>(xbase + k * XROW);
#pragma unroll
        for (int r4 = 0; r4 < 4; r4++) {
            ulonglong2 v = xr[r4];
            FMA2(accA[r4 * 2 + 0], v.x, w2a);
            FMA2(accA[r4 * 2 + 1], v.y, w2a);
            FMA2(accB[r4 * 2 + 0], v.x, w2b);
            FMA2(accB[r4 * 2 + 1], v.y, w2b);
        }
    }

    float* o0 = outbuf + j0 * XROW + rg * 16;
    float* o1 = o0 + XROW;
#pragma unroll
    for (int r2 = 0; r2 < 8; r2++) {
        float lo, hi;
        UNPACK2(lo, hi, accA[r2]);
        if (DO_RELU) { lo = fmaxf(lo, 0.f); hi = fmaxf(hi, 0.f); }
        o0[r2 * 2 + 0] = lo; o0[r2 * 2 + 1] = hi;
        UNPACK2(lo, hi, accB[r2]);
        if (DO_RELU) { lo = fmaxf(lo, 0.f); hi = fmaxf(hi, 0.f); }
        o1[r2 * 2 + 0] = lo; o1[r2 * 2 + 1] = hi;
    }
}

// ---------------- per-sample score: 4 independent row-groups, named barriers only ----------------
__global__ void __launch_bounds__(NTHR, 1) score_kernel(int iter,
    const float* __restrict__ s0,  const float* __restrict__ eps,
    const float* __restrict__ mu_w1,
    const float* __restrict__ mu_w2,  const float* __restrict__ mu_b2,
    const float* __restrict__ mu_w3,  const float* __restrict__ mu_b3,
    const float* __restrict__ sig_w1, const float* __restrict__ sig_b1,
    const float* __restrict__ sig_w2, const float* __restrict__ sig_b2,
    const float* __restrict__ sig_w3, const float* __restrict__ sig_b3,
    const float* __restrict__ risk_w1,
    const float* __restrict__ risk_w2, const float* __restrict__ risk_b2,
    const float* __restrict__ risk_w3, const float* __restrict__ risk_b3)
{
    extern __shared__ float smem[];
    float* xs   = smem;                       // [16][XROW]  (z only)
    float* bufA = smem + ZD * XROW;           // [256][XROW]
    float* bufB = bufA + HID * XROW;          // [256][XROW]

    __shared__ float red_s[NTHR];             // partitioned per group: [rg*128 .. rg*128+128)
    __shared__ float intent_s[TILE], agency_s[TILE];

    int bidx   = blockIdx.x;
    int b      = bidx >> 3;                   // SS/TILE = 8
    int s_base = (bidx & 7) * TILE;
    int t      = threadIdx.x;
    int rg     = t >> 7;                      // row-group 0..3, owns rows [rg*16, rg*16+16)
    int u      = t & 127;                     // index within group
    float* redg = red_s + rg * 128;

    // stage z (group rows only): 2 elems per thread; mu/std read straight from global
    {
#pragma unroll
        for (int i = 0; i < 2; i++) {
            int e  = u + 128 * i;
            int d  = e & 15;
            int rr = e >> 4;                  // 0..15
            int r  = rg * 16 + rr;
            int s  = s_base + r;
            float ev = eps[((((size_t)iter * BB + b) * SS) + s) * ZD + d];
            float v  = g_mu[b * ZD + d] + g_std[b * ZD + d] * ev;
            g_z[((size_t)(b * SS + s)) * ZD + d] = v;
            xs[d * XROW + r] = v;
        }
    }
    GBAR(rg);

    // ---- mu path ----
    gemm_tile<ZD, true>(xs, mu_w1 + OBS * HID, g_base_mu + b * HID, bufA);
    GBAR(rg);
    gemm_tile<HID, true>(bufA, mu_w2, mu_b2, bufB);
    GBAR(rg);
    {   // head: cols 126,127 of mu_w3; group-local (4 ksegs x 2 cols x 16 rows = 128)
        int kseg = u >> 5;
        int c    = (u >> 4) & 1;
        int rr   = u & 15;
        int r    = rg * 16 + rr;
        const float* wc = mu_w3 + (TPD - 2) + c;
        float acc = 0.f;
        int k0 = kseg * 64;
        for (int k = k0; k < k0 + 64; k++) acc += bufB[k * XROW + r] * wc[k * TPD];
        redg[u] = acc;
    }
    GBAR(rg);
    if (u < 16) {   // fused combine + intent (group rows)
        int r = rg * 16 + u;
        float m0 = mu_b3[TPD - 2], m1 = mu_b3[TPD - 1];
#pragma unroll
        for (int s = 0; s < 4; s++) {
            m0 += redg[s * 32 + u];
            m1 += redg[s * 32 + 16 + u];
        }
        float d0 = m0 - s0[b * OBS + 2];
        float d1 = m1 - s0[b * OBS + 3];
        intent_s[r] = d0 * d0 + d1 * d1;
    }
    // redg next rewritten 2 group-barriers later (agency) — safe without extra bar

    // ---- sigma path ----
    gemm_tile<ZD, true>(xs, sig_w1, sig_b1, bufA);
    GBAR(rg);
    gemm_tile<HID, true>(bufA, sig_w2, sig_b2, bufB);
    GBAR(rg);
    {   // layer3: 128 cols, K=256 split in 2 halves; 64 pairs x 2 khalves = 128 thr/group
        // each thread: 2 adjacent cols x 16 group-rows over its K half; partials -> bufA
        int j0 = (u & 63) * 2;                // cols j0, j0+1 (0..127)
        int kg = u >> 6;                      // K half
        const float* base = bufB + (size_t)kg * 128 * XROW + rg * 16;
        const float* W = sig_w3 + (size_t)kg * 128 * TPD;

        unsigned long long accA[8], accB[8];
#pragma unroll
        for (int r = 0; r < 8; r++) { accA[r] = 0ull; accB[r] = 0ull; }

        constexpr int PF = 8;
        float2 wr[PF];
#pragma unroll
        for (int p = 0; p < PF; p++) wr[p] = *reinterpret_cast<const float2*>(W + p * TPD + j0);

#pragma unroll 8
        for (int k = 0; k < 128; k++) {
            float2 wc = wr[k & 7];
            int kn = k + PF;
            if (kn < 128) wr[k & 7] = *reinterpret_cast<const float2*>(W + kn * TPD + j0);
            unsigned long long w2a, w2b; PACK2(w2a, wc.x, wc.x); PACK2(w2b, wc.y, wc.y);
            const ulonglong2* xr = reinterpret_cast<const ulonglong2*>(base + k * XROW);
#pragma unroll
            for (int r4 = 0; r4 < 4; r4++) {
                ulonglong2 v = xr[r4];
                FMA2(accA[r4 * 2 + 0], v.x, w2a);
                FMA2(accA[r4 * 2 + 1], v.y, w2a);
                FMA2(accB[r4 * 2 + 0], v.x, w2b);
                FMA2(accB[r4 * 2 + 1], v.y, w2b);
            }
        }
        float* o0 = bufA + (kg * 128 + j0) * XROW + rg * 16;
        float* o1 = o0 + XROW;
#pragma unroll
        for (int r2 = 0; r2 < 8; r2++) {
            float lo, hi;
            UNPACK2(lo, hi, accA[r2]);
            o0[r2 * 2 + 0] = lo; o0[r2 * 2 + 1] = hi;
            UNPACK2(lo, hi, accB[r2]);
            o1[r2 * 2 + 0] = lo; o1[r2 * 2 + 1] = hi;
        }
    }
    GBAR(rg);
    {   // agency: combine K-halves + bias + clip, reduce 128 cols (8 colgroups x 16 rows)
        int cg = u >> 4;
        int rr = u & 15;
        int r  = rg * 16 + rr;
        float sum = 0.f;
        for (int j = cg * 16; j < cg * 16 + 16; j++) {
            float v = sig_b3[j] + bufA[j * XROW + r] + bufA[(j + 128) * XROW + r];
            sum += fminf(fmaxf(v, -4.f), 3.f);
        }
        redg[u] = sum;
    }
    GBAR(rg);
    if (u < 16) {
        int r = rg * 16 + u;
        float sum = 0.f;
#pragma unroll
        for (int cg = 0; cg < 8; cg++) sum += redg[cg * 16 + u];
        agency_s[r] = -sum * (1.f / TPD);
    }

    // ---- risk path ----
    gemm_tile<ZD, true>(xs, risk_w1 + OBS * HID, g_base_risk + b * HID, bufA);
    GBAR(rg);
    gemm_tile<HID, true>(bufA, risk_w2, risk_b2, bufB);
    GBAR(rg);
    {   // layer3: group rows, k split over 8 segs of 32
        int kseg = u >> 4;
        int rr   = u & 15;
        int r    = rg * 16 + rr;
        float acc = 0.f;
        int k0 = kseg * 32;
        for (int k = k0; k < k0 + 32; k++) acc += bufB[k * XROW + r] * risk_w3[k];
        redg[u] = acc;
    }
    GBAR(rg);
    if (u < 16) {
        int r = rg * 16 + u;
        float acc = risk_b3[0];
#pragma unroll
        for (int p = 0; p < 8; p++) acc += redg[p * 16 + u];
        float risk = 1.f / (1.f + expf(-acc));
        float score = -intent_s[r] + 0.5f * agency_s[r] - risk;
        g_score[b * SS + s_base + r] = score;
    }
}

// ---------------- top-k + CEM update ----------------
__global__ void topk_kernel(int write_out, float* __restrict__ out)
{
    __shared__ float keys[SS];
    __shared__ int   ids[SS];
    __shared__ float ps[16 * ZD];
    __shared__ float mean_s[ZD];
    __shared__ int   flag_s, bidx_s;

    int b = blockIdx.x;
    int t = threadIdx.x;

    keys[t]       = g_score[b * SS + t];       ids[t]       = t;
    keys[t + 256] = g_score[b * SS + t + 256]; ids[t + 256] = t + 256;

    // bitonic sort ascending (512 elems, 256 threads)
    for (int k2 = 2; k2 <= SS; k2 <<= 1)
        for (int j = k2 >> 1; j > 0; j >>= 1) {
            __syncthreads();
            int i = ((t & ~(j - 1)) << 1) | (t & (j - 1));
            int p = i | j;
            bool up = ((i & k2) == 0);
            float a = keys[i], c = keys[p];
            if ((a > c) == up) {
                keys[i] = c; keys[p] = a;
                int tmp = ids[i]; ids[i] = ids[p]; ids[p] = tmp;
            }
        }
    __syncthreads();

    // elite mean (top-64 = positions [448, 512))
    int d = t & 15, part = t >> 4;
    float sum = 0.f;
    for (int e = part * 4; e < part * 4 + 4; e++) {
        int si = ids[SS - NEL + e];
        sum += g_z[((size_t)(b * SS + si)) * ZD + d];
    }
    ps[part * ZD + d] = sum;
    __syncthreads();
    if (t < ZD) {
        float m = 0.f;
        for (int p2 = 0; p2 < 16; p2++) m += ps[p2 * ZD + t];
        mean_s[t] = m * (1.f / NEL);
    }
    __syncthreads();

    // elite var (ddof=1)
    sum = 0.f;
    for (int e = part * 4; e < part * 4 + 4; e++) {
        int si = ids[SS - NEL + e];
        float v = g_z[((size_t)(b * SS + si)) * ZD + d] - mean_s[d];
        sum += v * v;
    }
    ps[part * ZD + d] = sum;
    __syncthreads();

    if (t == 0) {
        float v0 = keys[SS - 1];
        int better = v0 > g_best_score[b];
        flag_s = better; bidx_s = ids[SS - 1];
        if (better) g_best_score[b] = v0;
    }
    __syncthreads();

    if (t < ZD) {
        float var  = 0.f;
        for (int p2 = 0; p2 < 16; p2++) var += ps[p2 * ZD + t];
        float nstd = sqrtf(var * (1.f / (NEL - 1)));
        float nmu  = mean_s[t];
        float om = g_mu[b * ZD + t], os = g_std[b * ZD + t];
        g_mu[b * ZD + t]  = 0.25f * om + 0.75f * nmu;
        g_std[b * ZD + t] = fmaxf(0.25f * os + 0.75f * nstd, 0.2f);
        if (flag_s) g_best_z[b * ZD + t] = g_z[((size_t)(b * SS + bidx_s)) * ZD + t];
    }

    if (write_out) {
        __syncthreads();
        if (t < ZD)  out[b * 17 + t]  = g_best_z[b * ZD + t];
        if (t == ZD) out[b * 17 + ZD] = g_best_score[b];
    }
}

// ---------------- launch ----------------
extern "C" void kernel_launch(void* const* d_in, const int* in_sizes, int n_in,
                              void* d_out, int out_size)
{
    const float* s0      = (const float*)d_in[0];
    const float* eps     = (const float*)d_in[1];
    const float* enc_w1  = (const float*)d_in[2];
    const float* enc_b1  = (const float*)d_in[3];
    const float* enc_w2  = (const float*)d_in[4];
    const float* enc_b2  = (const float*)d_in[5];
    const float* zmu_w   = (const float*)d_in[6];
    const float* zmu_b   = (const float*)d_in[7];
    const float* zls_w   = (const float*)d_in[8];
    const float* zls_b   = (const float*)d_in[9];
    const float* mu_w1   = (const float*)d_in[10];
    const float* mu_b1   = (const float*)d_in[11];
    const float* mu_w2   = (const float*)d_in[12];
    const float* mu_b2   = (const float*)d_in[13];
    const float* mu_w3   = (const float*)d_in[14];
    const float* mu_b3   = (const float*)d_in[15];
    const float* sig_w1  = (const float*)d_in[16];
    const float* sig_b1  = (const float*)d_in[17];
    const float* sig_w2  = (const float*)d_in[18];
    const float* sig_b2  = (const float*)d_in[19];
    const float* sig_w3  = (const float*)d_in[20];
    const float* sig_b3  = (const float*)d_in[21];
    const float* risk_w1 = (const float*)d_in[22];
    const float* risk_b1 = (const float*)d_in[23];
    const float* risk_w2 = (const float*)d_in[24];
    const float* risk_b2 = (const float*)d_in[25];
    const float* risk_w3 = (const float*)d_in[26];
    const float* risk_b3 = (const float*)d_in[27];

    const int SMEM_BYTES = (ZD + 2 * HID) * XROW * (int)sizeof(float);  // 143,616 B
    cudaFuncSetAttribute(score_kernel, cudaFuncAttributeMaxDynamicSharedMemorySize, SMEM_BYTES);

    encoder_kernel<<<BB, 256>>>(s0, enc_w1, enc_b1, enc_w2, enc_b2,
                                zmu_w, zmu_b, zls_w, zls_b,
                                mu_w1, mu_b1, risk_w1, risk_b1);

    for (int i = 0; i < NITER; i++) {
        score_kernel<<<BB * (SS / TILE), NTHR, SMEM_BYTES>>>(i, s0, eps,
            mu_w1, mu_w2, mu_b2, mu_w3, mu_b3,
            sig_w1, sig_b1, sig_w2, sig_b2, sig_w3, sig_b3,
            risk_w1, risk_w2, risk_b2, risk_w3, risk_b3);
        topk_kernel<<<BB, 256>>>(i == NITER - 1 ? 1 : 0, (float*)d_out);
    }
}